// round 14
// baseline (speedup 1.0000x reference)
#include <cuda_runtime.h>
#include <cuda_bf16.h>
#include <math.h>
#include <cstdint>

#define ED    64      // embed dim
#define NKK   32      // w2 output dim
#define N_MAX 2048

// ---------------- device scratch (no allocations allowed) ----------------
__device__ float g_P[41 * ED];      // projected tables (stage 1)
__device__ float g_Atab[41 * ED];
__device__ float g_Btab[41 * ED];
// Packed bf16x2 per-row features: [n][d/2] (lo half = even d)
__device__ uint32_t g_HIh[N_MAX * (ED / 2)];
__device__ uint32_t g_HJh[N_MAX * (ED / 2)];

#define BF16X2_ONE 0x3F803F80u

__device__ __forceinline__ float warp_sum(float v) {
#pragma unroll
    for (int s = 16; s; s >>= 1) v += __shfl_xor_sync(0xffffffffu, v, s);
    return v;
}

__device__ __forceinline__ uint32_t bf2(float lo, float hi) {
    uint32_t r;
    asm("cvt.rn.bf16x2.f32 %0, %1, %2;" : "=r"(r) : "f"(hi), "f"(lo));
    return r;
}
// fused a*1 + b with relu output (single instruction).
__device__ __forceinline__ uint32_t hadd2_relu(uint32_t a, uint32_t b) {
    uint32_t r;
    asm("fma.rn.relu.bf16x2 %0, %1, %2, %3;"
        : "=r"(r) : "r"(a), "r"(BF16X2_ONE), "r"(b));
    return r;
}
// fused pack two f32 -> bf16x2 with relu output (single instruction).
__device__ __forceinline__ uint32_t pk_relu(float lo, float hi) {
    uint32_t r;
    asm("cvt.rn.relu.bf16x2.f32 %0, %1, %2;" : "=r"(r) : "f"(hi), "f"(lo));
    return r;
}

// ---------------- stage P1: projected tables, one warp per output ----------
__global__ void p1_kernel(const float* __restrict__ st,
                          const float* __restrict__ rt,
                          const float* __restrict__ ot,
                          const float* __restrict__ pw)   // [64][192]
{
    int warp = (blockIdx.x * blockDim.x + threadIdx.x) >> 5;
    int lane = threadIdx.x & 31;
    if (warp >= 41 * ED) return;
    int row = warp >> 6, k = warp & 63;
    const float* tab;
    int off;
    if (row < 16)      { tab = st + row * ED;        off = 0;   }
    else if (row < 25) { tab = rt + (row - 16) * ED; off = 64;  }
    else               { tab = ot + (row - 25) * ED; off = 128; }
    const float* wrow = pw + k * 192 + off;
    float v = tab[lane] * wrow[lane] + tab[lane + 32] * wrow[lane + 32];
    v = warp_sum(v);
    if (lane == 0) g_P[warp] = v;
}

// ---------------- stage P2: A/B tables, one warp per output ----------------
__global__ void p2_kernel(const float* __restrict__ pb,   // [64]
                          const float* __restrict__ w1,   // [64][128]
                          const float* __restrict__ b1)   // [64]
{
    int warp = (blockIdx.x * blockDim.x + threadIdx.x) >> 5;
    int lane = threadIdx.x & 31;
    if (warp >= 2 * 41 * ED) return;
    int side = warp / (41 * ED);
    int rem  = warp % (41 * ED);
    int row = rem >> 6, d = rem & 63;
    const float* w1row = w1 + d * 128 + side * 64;
    const float* Prow  = g_P + row * ED;
    float v = Prow[lane] * w1row[lane] + Prow[lane + 32] * w1row[lane + 32];
    if (row >= 25)
        v += pb[lane] * w1row[lane] + pb[lane + 32] * w1row[lane + 32];
    v = warp_sum(v);
    if (lane == 0) {
        if (row >= 25 && side == 1) v += b1[d];
        if (side) g_Btab[rem] = v;
        else      g_Atab[rem] = v;
    }
}

// ---------------- gather -> HI/HJ packed bf16x2, [n][d/2] ------------------
__global__ void gather_kernel(const int* __restrict__ si,
                              const int* __restrict__ ri,
                              const int* __restrict__ oi, int n)
{
    int g = blockIdx.x * blockDim.x + threadIdx.x;
    if (g >= n * (ED / 4)) return;
    int nn = g >> 4;
    int c  = (g & 15) * 4;
    int s = si[nn], r = ri[nn], o = oi[nn];

    float4 a0 = *(const float4*)&g_Atab[s * ED + c];
    float4 a1 = *(const float4*)&g_Atab[(16 + r) * ED + c];
    float4 a2 = *(const float4*)&g_Atab[(25 + o) * ED + c];
    uint2 hi;
    hi.x = bf2(a0.x + a1.x + a2.x, a0.y + a1.y + a2.y);
    hi.y = bf2(a0.z + a1.z + a2.z, a0.w + a1.w + a2.w);
    *(uint2*)&g_HIh[nn * 32 + c / 2] = hi;

    float4 b0 = *(const float4*)&g_Btab[s * ED + c];
    float4 b1v = *(const float4*)&g_Btab[(16 + r) * ED + c];
    float4 b2v = *(const float4*)&g_Btab[(25 + o) * ED + c];
    uint2 hj;
    hj.x = bf2(b0.x + b1v.x + b2v.x, b0.y + b1v.y + b2v.y);
    hj.y = bf2(b0.z + b1v.z + b2v.z, b0.w + b1v.w + b2v.w);
    *(uint2*)&g_HJh[nn * 32 + c / 2] = hj;
}

// ---------------- score kernel: chained mma.sync bf16 ----------------------
// CTA tile = 64 i x 64 j (jt loop x4). Warp w owns i-rows w*8..w*8+7.
// MMA1: b2 enters through the C operand of the first kt-step (no acc init).
// MMA2 (chained): D1 relu-packed in place is the A fragment of a second MMA
// vs w3-duplicated B; b3 enters through its C operand; score lands at c==0.
#define TI 64
#define TJ 64
#define SJ2 72  // hjT2 row stride (words): 72 % 32 == 8 -> bank 8c+gr+const
#define SHI 34  // sHIh row stride (words): even (8B align), bank-staggered

__global__ void __launch_bounds__(256, 3)
score_kernel(const float* __restrict__ w2,   // [32][64]
             const float* __restrict__ b2,   // [32]
             const float* __restrict__ w3,   // [1][32]
             const float* __restrict__ b3,   // [1]
             float* __restrict__ out, int n)
{
    const int t = threadIdx.x, w = t >> 5, lane = t & 31;
    const int gr = lane >> 2, c = lane & 3;
    const int i0 = blockIdx.y * TI, j0 = blockIdx.x * TJ;

    // Tile entirely at/below diagonal -> pure zeros.
    if (j0 + TJ - 1 <= i0) {
        const float4 z = make_float4(0.f, 0.f, 0.f, 0.f);
#pragma unroll
        for (int q = 0; q < 4; q++) {
            int idx = q * 256 + t;
            int r = idx >> 4, f4 = (idx & 15) * 4;
            *(float4*)&out[(size_t)(i0 + r) * n + j0 + f4] = z;
        }
        return;
    }

    __shared__ __align__(16) uint32_t sHIh[TI * SHI];     // permuted, 8.5KB
    __shared__ uint32_t sHJT2[32 * SJ2];                  // [d2][j], 9KB
    // B fragments, uint4 per (kt, ntp, lane): (nt r0, nt r1, nt+1 r0, nt+1 r1)
    __shared__ __align__(16) uint32_t sW2f4[4 * 2 * 32 * 4];  // 4KB

    // Stage hi rows, permuting word w -> pos = kt*8 + cc*2 + rr
    // (w = kt*8 + cc + 4*rr). Fragment pair (d2, d2+4) becomes adjacent.
#pragma unroll
    for (int q = 0; q < 2; q++) {
        int idx = q * 256 + t;
        int r = idx >> 3, w4 = (idx & 7) * 4;     // words w4..w4+3: same kt,rr
        uint4 v = *(const uint4*)&g_HIh[(i0 + r) * 32 + w4];
        int kt = w4 >> 3, rr = (w4 >> 2) & 1;
        uint32_t* dst = &sHIh[r * SHI + kt * 8 + rr];
        dst[0] = v.x; dst[2] = v.y; dst[4] = v.z; dst[6] = v.w;
    }
    // Stage hj transposed (64 j): sHJT2[d2][j] = packed hj(j0+j, 2d2, 2d2+1).
#pragma unroll
    for (int q = 0; q < 2; q++) {
        int idx = q * 256 + t;
        int j = idx & 63, dg = idx >> 6;       // dg 0..7 over both q
        uint4 v = *(const uint4*)&g_HJh[(j0 + j) * 32 + dg * 4];
        sHJT2[(dg * 4 + 0) * SJ2 + j] = v.x;
        sHJT2[(dg * 4 + 1) * SJ2 + j] = v.y;
        sHJT2[(dg * 4 + 2) * SJ2 + j] = v.z;
        sHJT2[(dg * 4 + 3) * SJ2 + j] = v.w;
    }
    // Stage B fragments (one uint4 per thread): kt = t>>6, ntp = (t>>5)&1.
    {
        int kt = t >> 6, ntp = (t >> 5) & 1, ln = t & 31;
        int col  = kt * 16 + 2 * (ln & 3);
        int row0 = (ntp * 2) * 8 + (ln >> 2);
        const float* wr0 = w2 + row0 * ED + col;
        const float* wr1 = wr0 + 8 * ED;       // row0 + 8 = next nt
        uint4 v;
        v.x = bf2(wr0[0], wr0[1]); v.y = bf2(wr0[8], wr0[9]);
        v.z = bf2(wr1[0], wr1[1]); v.w = bf2(wr1[8], wr1[9]);
        *(uint4*)&sW2f4[((kt * 2 + ntp) * 32 + ln) * 4] = v;
    }
    // Persistent C-operand registers (= b2 for cols nt*8 + 2c, +1).
    float b2v[8];
#pragma unroll
    for (int nt = 0; nt < 4; nt++) {
        float2 bb = *(const float2*)&b2[nt * 8 + 2 * c];
        b2v[nt * 2] = bb.x; b2v[nt * 2 + 1] = bb.y;
    }
    // MMA2 B fragments: w3 duplicated across all N-columns (no gr term).
    uint32_t w3f[2][2];
#pragma unroll
    for (int kt2 = 0; kt2 < 2; kt2++) {
        const float* wr = w3 + kt2 * 16 + 2 * c;
        w3f[kt2][0] = bf2(wr[0], wr[1]);
        w3f[kt2][1] = bf2(wr[8], wr[9]);
    }
    const float b3v = b3[0];
    __syncthreads();

#pragma unroll
    for (int jt = 0; jt < 4; jt++) {
        const int jb = jt * 16 + gr;
        // hj fragments for this jt, all kt: cached across the il loop.
        uint32_t hjr[4][4];
#pragma unroll
        for (int kt = 0; kt < 4; kt++) {
            const int d2a = kt * 8 + c;
            hjr[kt][0] = sHJT2[d2a * SJ2 + jb];
            hjr[kt][1] = sHJT2[d2a * SJ2 + jb + 8];
            hjr[kt][2] = sHJT2[(d2a + 4) * SJ2 + jb];
            hjr[kt][3] = sHJT2[(d2a + 4) * SJ2 + jb + 8];
        }
#pragma unroll 1
        for (int il = 0; il < 8; il++) {
            const int i = i0 + w * 8 + il;
            const uint32_t* hiRow = sHIh + (w * 8 + il) * SHI;
            uint2 hirp[4];
#pragma unroll
            for (int kt = 0; kt < 4; kt++)
                hirp[kt] = *(const uint2*)&hiRow[kt * 8 + c * 2];

            float cr[4][4];
            // kt = 0: C operand = b2 registers, D = cr (no init MOVs).
            {
                uint32_t a0 = hadd2_relu(hirp[0].x, hjr[0][0]);
                uint32_t a1 = hadd2_relu(hirp[0].x, hjr[0][1]);
                uint32_t a2 = hadd2_relu(hirp[0].y, hjr[0][2]);
                uint32_t a3 = hadd2_relu(hirp[0].y, hjr[0][3]);
#pragma unroll
                for (int ntp = 0; ntp < 2; ntp++) {
                    uint4 bw = *(const uint4*)&sW2f4[(ntp * 32 + lane) * 4];
                    asm volatile(
                        "mma.sync.aligned.m16n8k16.row.col.f32.bf16.bf16.f32 "
                        "{%0,%1,%2,%3}, {%4,%5,%6,%7}, {%8,%9}, {%10,%11,%10,%11};"
                        : "=f"(cr[ntp * 2][0]), "=f"(cr[ntp * 2][1]),
                          "=f"(cr[ntp * 2][2]), "=f"(cr[ntp * 2][3])
                        : "r"(a0), "r"(a1), "r"(a2), "r"(a3),
                          "r"(bw.x), "r"(bw.y),
                          "f"(b2v[ntp * 4]), "f"(b2v[ntp * 4 + 1]));
                    asm volatile(
                        "mma.sync.aligned.m16n8k16.row.col.f32.bf16.bf16.f32 "
                        "{%0,%1,%2,%3}, {%4,%5,%6,%7}, {%8,%9}, {%10,%11,%10,%11};"
                        : "=f"(cr[ntp * 2 + 1][0]), "=f"(cr[ntp * 2 + 1][1]),
                          "=f"(cr[ntp * 2 + 1][2]), "=f"(cr[ntp * 2 + 1][3])
                        : "r"(a0), "r"(a1), "r"(a2), "r"(a3),
                          "r"(bw.z), "r"(bw.w),
                          "f"(b2v[ntp * 4 + 2]), "f"(b2v[ntp * 4 + 3]));
                }
            }
#pragma unroll
            for (int kt = 1; kt < 4; kt++) {
                uint32_t a0 = hadd2_relu(hirp[kt].x, hjr[kt][0]);
                uint32_t a1 = hadd2_relu(hirp[kt].x, hjr[kt][1]);
                uint32_t a2 = hadd2_relu(hirp[kt].y, hjr[kt][2]);
                uint32_t a3 = hadd2_relu(hirp[kt].y, hjr[kt][3]);
#pragma unroll
                for (int ntp = 0; ntp < 2; ntp++) {
                    uint4 bw = *(const uint4*)
                        &sW2f4[((kt * 2 + ntp) * 32 + lane) * 4];
                    asm volatile(
                        "mma.sync.aligned.m16n8k16.row.col.f32.bf16.bf16.f32 "
                        "{%0,%1,%2,%3}, {%4,%5,%6,%7}, {%8,%9}, {%0,%1,%2,%3};"
                        : "+f"(cr[ntp * 2][0]), "+f"(cr[ntp * 2][1]),
                          "+f"(cr[ntp * 2][2]), "+f"(cr[ntp * 2][3])
                        : "r"(a0), "r"(a1), "r"(a2), "r"(a3),
                          "r"(bw.x), "r"(bw.y));
                    asm volatile(
                        "mma.sync.aligned.m16n8k16.row.col.f32.bf16.bf16.f32 "
                        "{%0,%1,%2,%3}, {%4,%5,%6,%7}, {%8,%9}, {%0,%1,%2,%3};"
                        : "+f"(cr[ntp * 2 + 1][0]), "+f"(cr[ntp * 2 + 1][1]),
                          "+f"(cr[ntp * 2 + 1][2]), "+f"(cr[ntp * 2 + 1][3])
                        : "r"(a0), "r"(a1), "r"(a2), "r"(a3),
                          "r"(bw.z), "r"(bw.w));
                }
            }

            // Chained MMA2: h2 = relu(cr) packed bf16 (D1 layout == A2
            // layout); B = w3 dup; b3 through C operand. s lands at c==0.
            float cr2[4];
            {
                uint32_t a0 = pk_relu(cr[0][0], cr[0][1]);
                uint32_t a1 = pk_relu(cr[0][2], cr[0][3]);
                uint32_t a2 = pk_relu(cr[1][0], cr[1][1]);
                uint32_t a3 = pk_relu(cr[1][2], cr[1][3]);
                asm volatile(
                    "mma.sync.aligned.m16n8k16.row.col.f32.bf16.bf16.f32 "
                    "{%0,%1,%2,%3}, {%4,%5,%6,%7}, {%8,%9}, {%10,%10,%10,%10};"
                    : "=f"(cr2[0]), "=f"(cr2[1]), "=f"(cr2[2]), "=f"(cr2[3])
                    : "r"(a0), "r"(a1), "r"(a2), "r"(a3),
                      "r"(w3f[0][0]), "r"(w3f[0][1]), "f"(b3v));
            }
            {
                uint32_t a0 = pk_relu(cr[2][0], cr[2][1]);
                uint32_t a1 = pk_relu(cr[2][2], cr[2][3]);
                uint32_t a2 = pk_relu(cr[3][0], cr[3][1]);
                uint32_t a3 = pk_relu(cr[3][2], cr[3][3]);
                asm volatile(
                    "mma.sync.aligned.m16n8k16.row.col.f32.bf16.bf16.f32 "
                    "{%0,%1,%2,%3}, {%4,%5,%6,%7}, {%8,%9}, {%0,%1,%2,%3};"
                    : "+f"(cr2[0]), "+f"(cr2[1]), "+f"(cr2[2]), "+f"(cr2[3])
                    : "r"(a0), "r"(a1), "r"(a2), "r"(a3),
                      "r"(w3f[1][0]), "r"(w3f[1][1]));
            }

            if (c == 0) {
                int j = j0 + jb;
                float v0 = (j > i) ? 1.f / (1.f + __expf(-cr2[0])) : 0.f;
                out[(size_t)i * n + j] = v0;
                int j8 = j + 8;
                float v1 = (j8 > i) ? 1.f / (1.f + __expf(-cr2[2])) : 0.f;
                out[(size_t)i * n + j8] = v1;
            }
        }
    }
}

// ---------------- launch ----------------------------------------------------
extern "C" void kernel_launch(void* const* d_in, const int* in_sizes, int n_in,
                              void* d_out, int out_size)
{
    const int*   si = (const int*)d_in[0];
    const int*   ri = (const int*)d_in[1];
    const int*   oi = (const int*)d_in[2];
    const float* st = (const float*)d_in[3];
    const float* rt = (const float*)d_in[4];
    const float* ot = (const float*)d_in[5];
    const float* pw = (const float*)d_in[6];
    const float* pb = (const float*)d_in[7];
    const float* w1 = (const float*)d_in[8];
    const float* b1 = (const float*)d_in[9];
    const float* w2 = (const float*)d_in[10];
    const float* b2 = (const float*)d_in[11];
    const float* w3 = (const float*)d_in[12];
    const float* b3 = (const float*)d_in[13];
    float* out = (float*)d_out;
    const int n = in_sizes[0];

    p1_kernel<<<(41 * ED * 32 + 255) / 256, 256>>>(st, rt, ot, pw);
    p2_kernel<<<(2 * 41 * ED * 32 + 255) / 256, 256>>>(pb, w1, b1);

    int total = n * (ED / 4);
    gather_kernel<<<(total + 255) / 256, 256>>>(si, ri, oi, n);

    dim3 grid(n / TJ, n / TI);
    score_kernel<<<grid, 256>>>(w2, b2, w3, b3, out, n);
}

// round 15
// speedup vs baseline: 1.0366x; 1.0366x over previous
#include <cuda_runtime.h>
#include <cuda_bf16.h>
#include <math.h>
#include <cstdint>

#define ED    64      // embed dim
#define NKK   32      // w2 output dim
#define N_MAX 2048

// ---------------- device scratch (no allocations allowed) ----------------
__device__ float g_P[41 * ED];      // projected tables (stage 1)
__device__ float g_Atab[41 * ED];
__device__ float g_Btab[41 * ED];
// Packed bf16x2 per-row features: [n][d/2] (lo half = even d)
__device__ uint32_t g_HIh[N_MAX * (ED / 2)];
__device__ uint32_t g_HJh[N_MAX * (ED / 2)];

#define BF16X2_ONE 0x3F803F80u

__device__ __forceinline__ float warp_sum(float v) {
#pragma unroll
    for (int s = 16; s; s >>= 1) v += __shfl_xor_sync(0xffffffffu, v, s);
    return v;
}

__device__ __forceinline__ uint32_t bf2(float lo, float hi) {
    uint32_t r;
    asm("cvt.rn.bf16x2.f32 %0, %1, %2;" : "=r"(r) : "f"(hi), "f"(lo));
    return r;
}
// fused a*1 + b with relu output (single instruction).
__device__ __forceinline__ uint32_t hadd2_relu(uint32_t a, uint32_t b) {
    uint32_t r;
    asm("fma.rn.relu.bf16x2 %0, %1, %2, %3;"
        : "=r"(r) : "r"(a), "r"(BF16X2_ONE), "r"(b));
    return r;
}
// fused pack two f32 -> bf16x2 with relu output (single instruction).
__device__ __forceinline__ uint32_t pk_relu(float lo, float hi) {
    uint32_t r;
    asm("cvt.rn.relu.bf16x2.f32 %0, %1, %2;" : "=r"(r) : "f"(hi), "f"(lo));
    return r;
}

// ---------------- stage P1: projected tables, one warp per output ----------
__global__ void p1_kernel(const float* __restrict__ st,
                          const float* __restrict__ rt,
                          const float* __restrict__ ot,
                          const float* __restrict__ pw)   // [64][192]
{
    int warp = (blockIdx.x * blockDim.x + threadIdx.x) >> 5;
    int lane = threadIdx.x & 31;
    if (warp >= 41 * ED) return;
    int row = warp >> 6, k = warp & 63;
    const float* tab;
    int off;
    if (row < 16)      { tab = st + row * ED;        off = 0;   }
    else if (row < 25) { tab = rt + (row - 16) * ED; off = 64;  }
    else               { tab = ot + (row - 25) * ED; off = 128; }
    const float* wrow = pw + k * 192 + off;
    float v = tab[lane] * wrow[lane] + tab[lane + 32] * wrow[lane + 32];
    v = warp_sum(v);
    if (lane == 0) g_P[warp] = v;
}

// ---------------- stage P2: A/B tables, one warp per output ----------------
__global__ void p2_kernel(const float* __restrict__ pb,   // [64]
                          const float* __restrict__ w1,   // [64][128]
                          const float* __restrict__ b1)   // [64]
{
    int warp = (blockIdx.x * blockDim.x + threadIdx.x) >> 5;
    int lane = threadIdx.x & 31;
    if (warp >= 2 * 41 * ED) return;
    int side = warp / (41 * ED);
    int rem  = warp % (41 * ED);
    int row = rem >> 6, d = rem & 63;
    const float* w1row = w1 + d * 128 + side * 64;
    const float* Prow  = g_P + row * ED;
    float v = Prow[lane] * w1row[lane] + Prow[lane + 32] * w1row[lane + 32];
    if (row >= 25)
        v += pb[lane] * w1row[lane] + pb[lane + 32] * w1row[lane + 32];
    v = warp_sum(v);
    if (lane == 0) {
        if (row >= 25 && side == 1) v += b1[d];
        if (side) g_Btab[rem] = v;
        else      g_Atab[rem] = v;
    }
}

// ---------------- gather -> HI/HJ packed bf16x2, [n][d/2] ------------------
__global__ void gather_kernel(const int* __restrict__ si,
                              const int* __restrict__ ri,
                              const int* __restrict__ oi, int n)
{
    int g = blockIdx.x * blockDim.x + threadIdx.x;
    if (g >= n * (ED / 4)) return;
    int nn = g >> 4;
    int c  = (g & 15) * 4;
    int s = si[nn], r = ri[nn], o = oi[nn];

    float4 a0 = *(const float4*)&g_Atab[s * ED + c];
    float4 a1 = *(const float4*)&g_Atab[(16 + r) * ED + c];
    float4 a2 = *(const float4*)&g_Atab[(25 + o) * ED + c];
    uint2 hi;
    hi.x = bf2(a0.x + a1.x + a2.x, a0.y + a1.y + a2.y);
    hi.y = bf2(a0.z + a1.z + a2.z, a0.w + a1.w + a2.w);
    *(uint2*)&g_HIh[nn * 32 + c / 2] = hi;

    float4 b0 = *(const float4*)&g_Btab[s * ED + c];
    float4 b1v = *(const float4*)&g_Btab[(16 + r) * ED + c];
    float4 b2v = *(const float4*)&g_Btab[(25 + o) * ED + c];
    uint2 hj;
    hj.x = bf2(b0.x + b1v.x + b2v.x, b0.y + b1v.y + b2v.y);
    hj.y = bf2(b0.z + b1v.z + b2v.z, b0.w + b1v.w + b2v.w);
    *(uint2*)&g_HJh[nn * 32 + c / 2] = hj;
}

// ---------------- score kernel: chained mma.sync bf16 ----------------------
// CTA tile = 64 i x 32 j (measured-best shape). Warp w owns i-rows
// w*8..w*8+7. MMA1: b2 enters through the C operand of the first kt-step
// (no acc-init MOVs). MMA2 (chained): D1 relu-packed in place is the A
// fragment of a second MMA vs w3-duplicated B; b3 through its C operand;
// score lands in lanes c==0 with no shuffle.
#define TI 64
#define TJ 32
#define SJ2 40  // hjT2 row stride (words): bank = 8c+gr, conflict-free
#define SHI 34  // sHIh row stride (words): even (8B align), bank-staggered

__global__ void __launch_bounds__(256, 3)
score_kernel(const float* __restrict__ w2,   // [32][64]
             const float* __restrict__ b2,   // [32]
             const float* __restrict__ w3,   // [1][32]
             const float* __restrict__ b3,   // [1]
             float* __restrict__ out, int n)
{
    const int t = threadIdx.x, w = t >> 5, lane = t & 31;
    const int gr = lane >> 2, c = lane & 3;
    const int i0 = blockIdx.y * TI, j0 = blockIdx.x * TJ;

    // Tile entirely at/below diagonal -> pure zeros.
    if (j0 + TJ - 1 <= i0) {
        const float4 z = make_float4(0.f, 0.f, 0.f, 0.f);
#pragma unroll
        for (int q = 0; q < 2; q++) {
            int idx = q * 256 + t;
            int r = idx >> 3, f4 = (idx & 7) * 4;
            *(float4*)&out[(size_t)(i0 + r) * n + j0 + f4] = z;
        }
        return;
    }

    __shared__ __align__(16) uint32_t sHIh[TI * SHI];     // permuted, 8.5KB
    __shared__ uint32_t sHJT2[32 * SJ2];                  // [d2][j], 5KB
    // B fragments, uint4 per (kt, ntp, lane): (nt r0, nt r1, nt+1 r0, nt+1 r1)
    __shared__ __align__(16) uint32_t sW2f4[4 * 2 * 32 * 4];  // 4KB

    // Stage hi rows, permuting word w -> pos = kt*8 + cc*2 + rr
    // (w = kt*8 + cc + 4*rr). Fragment pair (d2, d2+4) becomes adjacent.
#pragma unroll
    for (int q = 0; q < 2; q++) {
        int idx = q * 256 + t;
        int r = idx >> 3, w4 = (idx & 7) * 4;     // words w4..w4+3: same kt,rr
        uint4 v = *(const uint4*)&g_HIh[(i0 + r) * 32 + w4];
        int kt = w4 >> 3, rr = (w4 >> 2) & 1;
        uint32_t* dst = &sHIh[r * SHI + kt * 8 + rr];
        dst[0] = v.x; dst[2] = v.y; dst[4] = v.z; dst[6] = v.w;
    }
    // Stage hj transposed: sHJT2[d2][j] = packed hj(j0+j, 2*d2, 2*d2+1).
    {
        int j = t & 31, dg = t >> 5;           // dg*4 .. dg*4+3 d2-words
        uint4 v = *(const uint4*)&g_HJh[(j0 + j) * 32 + dg * 4];
        sHJT2[(dg * 4 + 0) * SJ2 + j] = v.x;
        sHJT2[(dg * 4 + 1) * SJ2 + j] = v.y;
        sHJT2[(dg * 4 + 2) * SJ2 + j] = v.z;
        sHJT2[(dg * 4 + 3) * SJ2 + j] = v.w;
    }
    // Stage B fragments (one uint4 per thread): kt = t>>6, ntp = (t>>5)&1.
    {
        int kt = t >> 6, ntp = (t >> 5) & 1, ln = t & 31;
        int col  = kt * 16 + 2 * (ln & 3);
        int row0 = (ntp * 2) * 8 + (ln >> 2);
        const float* wr0 = w2 + row0 * ED + col;
        const float* wr1 = wr0 + 8 * ED;       // row0 + 8 = next nt
        uint4 v;
        v.x = bf2(wr0[0], wr0[1]); v.y = bf2(wr0[8], wr0[9]);
        v.z = bf2(wr1[0], wr1[1]); v.w = bf2(wr1[8], wr1[9]);
        *(uint4*)&sW2f4[((kt * 2 + ntp) * 32 + ln) * 4] = v;
    }
    // Persistent C-operand registers (= b2 for cols nt*8 + 2c, +1).
    float b2v[8];
#pragma unroll
    for (int nt = 0; nt < 4; nt++) {
        float2 bb = *(const float2*)&b2[nt * 8 + 2 * c];
        b2v[nt * 2] = bb.x; b2v[nt * 2 + 1] = bb.y;
    }
    // MMA2 B fragments: w3 duplicated across all N-columns (no gr term).
    uint32_t w3f[2][2];
#pragma unroll
    for (int kt2 = 0; kt2 < 2; kt2++) {
        const float* wr = w3 + kt2 * 16 + 2 * c;
        w3f[kt2][0] = bf2(wr[0], wr[1]);
        w3f[kt2][1] = bf2(wr[8], wr[9]);
    }
    const float b3v = b3[0];
    __syncthreads();

#pragma unroll
    for (int jt = 0; jt < 2; jt++) {
        const int jb = jt * 16 + gr;
        // hj fragments for this jt, all kt: cached across the il loop.
        uint32_t hjr[4][4];
#pragma unroll
        for (int kt = 0; kt < 4; kt++) {
            const int d2a = kt * 8 + c;
            hjr[kt][0] = sHJT2[d2a * SJ2 + jb];
            hjr[kt][1] = sHJT2[d2a * SJ2 + jb + 8];
            hjr[kt][2] = sHJT2[(d2a + 4) * SJ2 + jb];
            hjr[kt][3] = sHJT2[(d2a + 4) * SJ2 + jb + 8];
        }
#pragma unroll 1
        for (int il = 0; il < 8; il++) {
            const int i = i0 + w * 8 + il;
            const uint32_t* hiRow = sHIh + (w * 8 + il) * SHI;
            uint2 hirp[4];
#pragma unroll
            for (int kt = 0; kt < 4; kt++)
                hirp[kt] = *(const uint2*)&hiRow[kt * 8 + c * 2];

            float cr[4][4];
            // kt = 0: C operand = b2 registers, D = cr (no init MOVs).
            {
                uint32_t a0 = hadd2_relu(hirp[0].x, hjr[0][0]);
                uint32_t a1 = hadd2_relu(hirp[0].x, hjr[0][1]);
                uint32_t a2 = hadd2_relu(hirp[0].y, hjr[0][2]);
                uint32_t a3 = hadd2_relu(hirp[0].y, hjr[0][3]);
#pragma unroll
                for (int ntp = 0; ntp < 2; ntp++) {
                    uint4 bw = *(const uint4*)&sW2f4[(ntp * 32 + lane) * 4];
                    asm volatile(
                        "mma.sync.aligned.m16n8k16.row.col.f32.bf16.bf16.f32 "
                        "{%0,%1,%2,%3}, {%4,%5,%6,%7}, {%8,%9}, {%10,%11,%10,%11};"
                        : "=f"(cr[ntp * 2][0]), "=f"(cr[ntp * 2][1]),
                          "=f"(cr[ntp * 2][2]), "=f"(cr[ntp * 2][3])
                        : "r"(a0), "r"(a1), "r"(a2), "r"(a3),
                          "r"(bw.x), "r"(bw.y),
                          "f"(b2v[ntp * 4]), "f"(b2v[ntp * 4 + 1]));
                    asm volatile(
                        "mma.sync.aligned.m16n8k16.row.col.f32.bf16.bf16.f32 "
                        "{%0,%1,%2,%3}, {%4,%5,%6,%7}, {%8,%9}, {%10,%11,%10,%11};"
                        : "=f"(cr[ntp * 2 + 1][0]), "=f"(cr[ntp * 2 + 1][1]),
                          "=f"(cr[ntp * 2 + 1][2]), "=f"(cr[ntp * 2 + 1][3])
                        : "r"(a0), "r"(a1), "r"(a2), "r"(a3),
                          "r"(bw.z), "r"(bw.w),
                          "f"(b2v[ntp * 4 + 2]), "f"(b2v[ntp * 4 + 3]));
                }
            }
#pragma unroll
            for (int kt = 1; kt < 4; kt++) {
                uint32_t a0 = hadd2_relu(hirp[kt].x, hjr[kt][0]);
                uint32_t a1 = hadd2_relu(hirp[kt].x, hjr[kt][1]);
                uint32_t a2 = hadd2_relu(hirp[kt].y, hjr[kt][2]);
                uint32_t a3 = hadd2_relu(hirp[kt].y, hjr[kt][3]);
#pragma unroll
                for (int ntp = 0; ntp < 2; ntp++) {
                    uint4 bw = *(const uint4*)
                        &sW2f4[((kt * 2 + ntp) * 32 + lane) * 4];
                    asm volatile(
                        "mma.sync.aligned.m16n8k16.row.col.f32.bf16.bf16.f32 "
                        "{%0,%1,%2,%3}, {%4,%5,%6,%7}, {%8,%9}, {%0,%1,%2,%3};"
                        : "+f"(cr[ntp * 2][0]), "+f"(cr[ntp * 2][1]),
                          "+f"(cr[ntp * 2][2]), "+f"(cr[ntp * 2][3])
                        : "r"(a0), "r"(a1), "r"(a2), "r"(a3),
                          "r"(bw.x), "r"(bw.y));
                    asm volatile(
                        "mma.sync.aligned.m16n8k16.row.col.f32.bf16.bf16.f32 "
                        "{%0,%1,%2,%3}, {%4,%5,%6,%7}, {%8,%9}, {%0,%1,%2,%3};"
                        : "+f"(cr[ntp * 2 + 1][0]), "+f"(cr[ntp * 2 + 1][1]),
                          "+f"(cr[ntp * 2 + 1][2]), "+f"(cr[ntp * 2 + 1][3])
                        : "r"(a0), "r"(a1), "r"(a2), "r"(a3),
                          "r"(bw.z), "r"(bw.w));
                }
            }

            // Chained MMA2: h2 = relu(cr) packed bf16 (D1 layout == A2
            // layout); B = w3 dup; b3 through C operand. s lands at c==0.
            float cr2[4];
            {
                uint32_t a0 = pk_relu(cr[0][0], cr[0][1]);
                uint32_t a1 = pk_relu(cr[0][2], cr[0][3]);
                uint32_t a2 = pk_relu(cr[1][0], cr[1][1]);
                uint32_t a3 = pk_relu(cr[1][2], cr[1][3]);
                asm volatile(
                    "mma.sync.aligned.m16n8k16.row.col.f32.bf16.bf16.f32 "
                    "{%0,%1,%2,%3}, {%4,%5,%6,%7}, {%8,%9}, {%10,%10,%10,%10};"
                    : "=f"(cr2[0]), "=f"(cr2[1]), "=f"(cr2[2]), "=f"(cr2[3])
                    : "r"(a0), "r"(a1), "r"(a2), "r"(a3),
                      "r"(w3f[0][0]), "r"(w3f[0][1]), "f"(b3v));
            }
            {
                uint32_t a0 = pk_relu(cr[2][0], cr[2][1]);
                uint32_t a1 = pk_relu(cr[2][2], cr[2][3]);
                uint32_t a2 = pk_relu(cr[3][0], cr[3][1]);
                uint32_t a3 = pk_relu(cr[3][2], cr[3][3]);
                asm volatile(
                    "mma.sync.aligned.m16n8k16.row.col.f32.bf16.bf16.f32 "
                    "{%0,%1,%2,%3}, {%4,%5,%6,%7}, {%8,%9}, {%0,%1,%2,%3};"
                    : "+f"(cr2[0]), "+f"(cr2[1]), "+f"(cr2[2]), "+f"(cr2[3])
                    : "r"(a0), "r"(a1), "r"(a2), "r"(a3),
                      "r"(w3f[1][0]), "r"(w3f[1][1]));
            }

            if (c == 0) {
                int j = j0 + jb;
                float v0 = (j > i) ? 1.f / (1.f + __expf(-cr2[0])) : 0.f;
                out[(size_t)i * n + j] = v0;
                int j8 = j + 8;
                float v1 = (j8 > i) ? 1.f / (1.f + __expf(-cr2[2])) : 0.f;
                out[(size_t)i * n + j8] = v1;
            }
        }
    }
}

// ---------------- launch ----------------------------------------------------
extern "C" void kernel_launch(void* const* d_in, const int* in_sizes, int n_in,
                              void* d_out, int out_size)
{
    const int*   si = (const int*)d_in[0];
    const int*   ri = (const int*)d_in[1];
    const int*   oi = (const int*)d_in[2];
    const float* st = (const float*)d_in[3];
    const float* rt = (const float*)d_in[4];
    const float* ot = (const float*)d_in[5];
    const float* pw = (const float*)d_in[6];
    const float* pb = (const float*)d_in[7];
    const float* w1 = (const float*)d_in[8];
    const float* b1 = (const float*)d_in[9];
    const float* w2 = (const float*)d_in[10];
    const float* b2 = (const float*)d_in[11];
    const float* w3 = (const float*)d_in[12];
    const float* b3 = (const float*)d_in[13];
    float* out = (float*)d_out;
    const int n = in_sizes[0];

    p1_kernel<<<(41 * ED * 32 + 255) / 256, 256>>>(st, rt, ot, pw);
    p2_kernel<<<(2 * 41 * ED * 32 + 255) / 256, 256>>>(pb, w1, b1);

    int total = n * (ED / 4);
    gather_kernel<<<(total + 255) / 256, 256>>>(si, ri, oi, n);

    dim3 grid(n / TJ, n / TI);
    score_kernel<<<grid, 256>>>(w2, b2, w3, b3, out, n);
}